// round 3
// baseline (speedup 1.0000x reference)
#include <cuda_runtime.h>
#include <cstdint>

#define DIM   512
#define NROWS 16384          // 4 * 4096
#define KCB   8192
#define MT    128            // rows per block
#define KT    128            // codes per k-tile
#define DC    8              // dims per smem chunk
#define NDT   (DIM / DC)     // 64 chunks

__device__ float g_ehalf[KCB];
__device__ int   g_ind[NROWS];

// ---------------------------------------------------------------------------
// Kernel 1: g_ehalf[k] = 0.5 * sum(embed[k]^2)   (warp per row)
// ---------------------------------------------------------------------------
__global__ void ehalf_kernel(const float* __restrict__ embed) {
    int w    = threadIdx.x >> 5;
    int lane = threadIdx.x & 31;
    int r    = blockIdx.x * 8 + w;
    const float* p = embed + (size_t)r * DIM;
    float s = 0.f;
#pragma unroll
    for (int i = 0; i < DIM / 32; i++) {
        float v = p[lane + i * 32];
        s += v * v;
    }
#pragma unroll
    for (int o = 16; o; o >>= 1) s += __shfl_xor_sync(0xffffffffu, s, o);
    if (lane == 0) g_ehalf[r] = 0.5f * s;
}

// ---------------------------------------------------------------------------
// Kernel 2: fused GEMM + row-argmax.
// score(n,k) = x_n . e_k - 0.5*||e_k||^2 ; argmax_k per row with first-index
// tie-break (matches jnp.argmax).
// Packed f32x2 FFMA: accumulators hold row-pairs, B value duplicated.
// ---------------------------------------------------------------------------
#define FMA2(acc, a, b) \
    asm volatile("fma.rn.f32x2 %0, %1, %2, %0;" : "+l"(acc) : "l"(a), "l"(b))
#define PACK2(d, lo, hi) \
    asm volatile("mov.b64 %0, {%1, %2};" : "=l"(d) : "f"(lo), "f"(hi))
#define UNPK2(lo, hi, s) \
    asm volatile("mov.b64 {%0, %1}, %2;" : "=f"(lo), "=f"(hi) : "l"(s))

#define REDUCE_MERGE(S, SLOT) do {                                            \
    float bvl = S[0]; int bil = k0 + tc * 4;                                  \
    _Pragma("unroll")                                                         \
    for (int j = 1; j < 8; j++) {                                             \
        int cg = k0 + ((j < 4) ? (tc * 4 + j) : (64 + tc * 4 + j - 4));       \
        if (S[j] > bvl) { bvl = S[j]; bil = cg; }                             \
    }                                                                         \
    _Pragma("unroll")                                                         \
    for (int off = 8; off >= 1; off >>= 1) {                                  \
        float ov = __shfl_xor_sync(0xffffffffu, bvl, off);                    \
        int   oi = __shfl_xor_sync(0xffffffffu, bil, off);                    \
        if (ov > bvl || (ov == bvl && oi < bil)) { bvl = ov; bil = oi; }      \
    }                                                                         \
    if (bvl > best_v[SLOT] || (bvl == best_v[SLOT] && bil < best_i[SLOT])) {  \
        best_v[SLOT] = bvl; best_i[SLOT] = bil;                               \
    }                                                                         \
} while (0)

__global__ __launch_bounds__(256, 1)
void argmax_kernel(const float* __restrict__ x,
                   const float* __restrict__ embed,
                   float* __restrict__ ind_out) {
    __shared__ __align__(16) float As[2][DC][MT];
    __shared__ __align__(16) float Bs[2][DC][KT];

    const int tid = threadIdx.x;
    const int tr  = tid >> 4;          // 0..15 (row group)
    const int tc  = tid & 15;          // 0..15 (col group)
    const int m0  = blockIdx.x * MT;

    // staging assignment: thread loads one float4 of the 128x8 chunk
    const int arow = tid >> 1;         // 0..127
    const int aseg = (tid & 1) * 4;    // 0 or 4
    const float* xg = x + (size_t)(m0 + arow) * DIM + aseg;

    const uint32_t as_base = (uint32_t)__cvta_generic_to_shared(&As[0][0][0]);

    float best_v[8];
    int   best_i[8];
#pragma unroll
    for (int i = 0; i < 8; i++) { best_v[i] = -3.4e38f; best_i[i] = 0; }

#pragma unroll 1
    for (int kt = 0; kt < KCB / KT; kt++) {
        const int k0 = kt * KT;
        const float* eg = embed + (size_t)(k0 + arow) * DIM + aseg;

        // -0.5*||e||^2 offsets for this thread's 8 columns
        float cf[8];
#pragma unroll
        for (int j = 0; j < 8; j++) {
            int col = (j < 4) ? (tc * 4 + j) : (64 + tc * 4 + j - 4);
            cf[j] = g_ehalf[k0 + col];
        }

        unsigned long long acc[4][8];
#pragma unroll
        for (int p = 0; p < 4; p++)
#pragma unroll
            for (int j = 0; j < 8; j++) acc[p][j] = 0ull;

        // stage chunk 0
        float4 av = *(const float4*)(xg);
        float4 bv = *(const float4*)(eg);
        __syncthreads();                      // prior k-tile done with buf 0
        As[0][aseg + 0][arow] = av.x; As[0][aseg + 1][arow] = av.y;
        As[0][aseg + 2][arow] = av.z; As[0][aseg + 3][arow] = av.w;
        Bs[0][aseg + 0][arow] = bv.x; Bs[0][aseg + 1][arow] = bv.y;
        Bs[0][aseg + 2][arow] = bv.z; Bs[0][aseg + 3][arow] = bv.w;
        __syncthreads();

        int buf = 0;
#pragma unroll 1
        for (int dt = 0; dt < NDT; dt++) {
            float4 av2, bv2;
            if (dt < NDT - 1) {
                av2 = *(const float4*)(xg + (dt + 1) * DC);
                bv2 = *(const float4*)(eg + (dt + 1) * DC);
            }
#pragma unroll
            for (int d = 0; d < DC; d++) {
                unsigned long long ap0, ap1, ap2, ap3;
                uint32_t ao = as_base + (uint32_t)(((buf * DC + d) * MT + tr * 4) * 4);
                asm volatile("ld.shared.v2.b64 {%0,%1},[%2];"
                             : "=l"(ap0), "=l"(ap1) : "r"(ao));
                asm volatile("ld.shared.v2.b64 {%0,%1},[%2];"
                             : "=l"(ap2), "=l"(ap3) : "r"(ao + 256u));
                float4 b03 = *(const float4*)&Bs[buf][d][tc * 4];
                float4 b47 = *(const float4*)&Bs[buf][d][64 + tc * 4];
                unsigned long long bd0, bd1, bd2, bd3, bd4, bd5, bd6, bd7;
                PACK2(bd0, b03.x, b03.x); PACK2(bd1, b03.y, b03.y);
                PACK2(bd2, b03.z, b03.z); PACK2(bd3, b03.w, b03.w);
                PACK2(bd4, b47.x, b47.x); PACK2(bd5, b47.y, b47.y);
                PACK2(bd6, b47.z, b47.z); PACK2(bd7, b47.w, b47.w);
                FMA2(acc[0][0], ap0, bd0); FMA2(acc[1][0], ap1, bd0);
                FMA2(acc[2][0], ap2, bd0); FMA2(acc[3][0], ap3, bd0);
                FMA2(acc[0][1], ap0, bd1); FMA2(acc[1][1], ap1, bd1);
                FMA2(acc[2][1], ap2, bd1); FMA2(acc[3][1], ap3, bd1);
                FMA2(acc[0][2], ap0, bd2); FMA2(acc[1][2], ap1, bd2);
                FMA2(acc[2][2], ap2, bd2); FMA2(acc[3][2], ap3, bd2);
                FMA2(acc[0][3], ap0, bd3); FMA2(acc[1][3], ap1, bd3);
                FMA2(acc[2][3], ap2, bd3); FMA2(acc[3][3], ap3, bd3);
                FMA2(acc[0][4], ap0, bd4); FMA2(acc[1][4], ap1, bd4);
                FMA2(acc[2][4], ap2, bd4); FMA2(acc[3][4], ap3, bd4);
                FMA2(acc[0][5], ap0, bd5); FMA2(acc[1][5], ap1, bd5);
                FMA2(acc[2][5], ap2, bd5); FMA2(acc[3][5], ap3, bd5);
                FMA2(acc[0][6], ap0, bd6); FMA2(acc[1][6], ap1, bd6);
                FMA2(acc[2][6], ap2, bd6); FMA2(acc[3][6], ap3, bd6);
                FMA2(acc[0][7], ap0, bd7); FMA2(acc[1][7], ap1, bd7);
                FMA2(acc[2][7], ap2, bd7); FMA2(acc[3][7], ap3, bd7);
            }
            if (dt < NDT - 1) {
                int nb = buf ^ 1;
                As[nb][aseg + 0][arow] = av2.x; As[nb][aseg + 1][arow] = av2.y;
                As[nb][aseg + 2][arow] = av2.z; As[nb][aseg + 3][arow] = av2.w;
                Bs[nb][aseg + 0][arow] = bv2.x; Bs[nb][aseg + 1][arow] = bv2.y;
                Bs[nb][aseg + 2][arow] = bv2.z; Bs[nb][aseg + 3][arow] = bv2.w;
                __syncthreads();
                buf = nb;
            }
        }

        // epilogue: scores = dot - 0.5*||e||^2 ; fold into running argmax
#pragma unroll
        for (int p = 0; p < 4; p++) {
            float sl[8], sh[8];
#pragma unroll
            for (int j = 0; j < 8; j++) {
                float lo, hi;
                UNPK2(lo, hi, acc[p][j]);
                sl[j] = lo - cf[j];
                sh[j] = hi - cf[j];
            }
            REDUCE_MERGE(sl, p * 2);
            REDUCE_MERGE(sh, p * 2 + 1);
        }
    }

    if (tc == 0) {
#pragma unroll
        for (int slot = 0; slot < 8; slot++) {
            int p = slot >> 1, h = slot & 1;
            int lr = (p < 2) ? (tr * 4 + p * 2 + h)
                             : (64 + tr * 4 + (p - 2) * 2 + h);
            int row = m0 + lr;
            g_ind[row] = best_i[slot];
            if (ind_out) ind_out[row] = (float)best_i[slot];
        }
    }
}

// ---------------------------------------------------------------------------
// Kernel 3: gather quantize = embed[ind]
// ---------------------------------------------------------------------------
__global__ void gather_kernel(const float* __restrict__ embed,
                              float* __restrict__ outq) {
    int row = blockIdx.x;
    int idx = g_ind[row];
    const float4* src = (const float4*)(embed + (size_t)idx * DIM);
    float4*       dst = (float4*)(outq + (size_t)row * DIM);
    dst[threadIdx.x] = src[threadIdx.x];
}

// ---------------------------------------------------------------------------
extern "C" void kernel_launch(void* const* d_in, const int* in_sizes, int n_in,
                              void* d_out, int out_size) {
    const float* x = nullptr;
    const float* embed = nullptr;
    for (int i = 0; i < n_in; i++) {
        if (in_sizes[i] == NROWS * DIM)      x = (const float*)d_in[i];
        else if (in_sizes[i] == KCB * DIM)   embed = (const float*)d_in[i];
    }

    float* out  = (float*)d_out;
    float* qout = nullptr;
    float* iout = nullptr;
    if (out_size >= NROWS * DIM + NROWS) { qout = out; iout = out + (size_t)NROWS * DIM; }
    else if (out_size >= NROWS * DIM)    { qout = out; }
    else                                 { iout = out; }

    ehalf_kernel<<<KCB / 8, 256>>>(embed);
    argmax_kernel<<<NROWS / MT, 256>>>(x, embed, iout);
    if (qout) gather_kernel<<<NROWS, 128>>>(embed, qout);
}

// round 9
// speedup vs baseline: 1.0065x; 1.0065x over previous
#include <cuda_runtime.h>
#include <cuda_fp16.h>
#include <cstdint>

#define DIM   512
#define NROWS 16384
#define KCB   8192
#define KP    1536            // split K' (fp16): [hi | lo | hi] x [hi | hi | lo]
#define CH    64              // K elems per chunk (128 bytes fp16)
#define NCH   (KP / CH)       // 24
#define NSTG  3
#define STAGE_BYTES 32768     // A(128x128B)=16K + B(128x128B)=16K
#define DYN_SMEM (NSTG * STAGE_BYTES + 1024)
#define MT    128
#define NT    128
#define NPQ   ((KCB / NT) * 4)   // 256 partials per row (4 col-quarters per tile)
#define EPS_MARGIN 0.02f

__device__ __half g_A[(size_t)NROWS * KP];
__device__ __half g_B[(size_t)KCB * KP];
__device__ float  g_ehalf[KCB];
__device__ float  g_pv1[(size_t)NROWS * NPQ];
__device__ float  g_pv2[(size_t)NROWS * NPQ];
__device__ int    g_pi1[(size_t)NROWS * NPQ];
__device__ int    g_ind[NROWS];
__device__ int    g_flagcnt;
__device__ int    g_flaglist[NROWS];

// ---------------------------------------------------------------- PTX helpers
__device__ __forceinline__ uint32_t smem_u32(const void* p) {
    return (uint32_t)__cvta_generic_to_shared(p);
}
#define CP16(dst, src) \
    asm volatile("cp.async.cg.shared.global [%0], [%1], 16;" :: "r"(dst), "l"(src))
#define CP_COMMIT() asm volatile("cp.async.commit_group;" ::: "memory")
#define CP_WAITG(n) asm volatile("cp.async.wait_group %0;" :: "n"(n) : "memory")

#define LDSM4(r0, r1, r2, r3, a)                                              \
    asm volatile("ldmatrix.sync.aligned.m8n8.x4.shared.b16 {%0,%1,%2,%3},[%4];" \
                 : "=r"(r0), "=r"(r1), "=r"(r2), "=r"(r3) : "r"(a))

#define MMA16816(d, a0, a1, a2, a3, b0, b1)                                   \
    asm volatile("mma.sync.aligned.m16n8k16.row.col.f32.f16.f16.f32 "         \
                 "{%0,%1,%2,%3},{%4,%5,%6,%7},{%8,%9},{%0,%1,%2,%3};"         \
                 : "+f"((d)[0]), "+f"((d)[1]), "+f"((d)[2]), "+f"((d)[3])     \
                 : "r"(a0), "r"(a1), "r"(a2), "r"(a3), "r"(b0), "r"(b1))

// --------------------------------------------------------------- split kernels
__global__ void split_x_kernel(const float* __restrict__ x) {
    int r = blockIdx.x * 2 + (threadIdx.x >> 7);
    int d = (threadIdx.x & 127) * 4;
    float4 v = *(const float4*)(x + (size_t)r * DIM + d);
    __half h0 = __float2half_rn(v.x), h1 = __float2half_rn(v.y);
    __half h2 = __float2half_rn(v.z), h3 = __float2half_rn(v.w);
    __half l0 = __float2half_rn(v.x - __half2float(h0));
    __half l1 = __float2half_rn(v.y - __half2float(h1));
    __half l2 = __float2half_rn(v.z - __half2float(h2));
    __half l3 = __float2half_rn(v.w - __half2float(h3));
    __half* base = g_A + (size_t)r * KP;
    *(__half2*)(base + d)            = __halves2half2(h0, h1);
    *(__half2*)(base + d + 2)        = __halves2half2(h2, h3);
    *(__half2*)(base + 512 + d)      = __halves2half2(l0, l1);
    *(__half2*)(base + 512 + d + 2)  = __halves2half2(l2, l3);
    *(__half2*)(base + 1024 + d)     = __halves2half2(h0, h1);
    *(__half2*)(base + 1024 + d + 2) = __halves2half2(h2, h3);
}

__global__ void split_e_kernel(const float* __restrict__ e) {
    if (blockIdx.x == 0 && threadIdx.x == 0) g_flagcnt = 0;
    int r = blockIdx.x * 2 + (threadIdx.x >> 7);
    int d = (threadIdx.x & 127) * 4;
    float4 v = *(const float4*)(e + (size_t)r * DIM + d);
    __half h0 = __float2half_rn(v.x), h1 = __float2half_rn(v.y);
    __half h2 = __float2half_rn(v.z), h3 = __float2half_rn(v.w);
    __half l0 = __float2half_rn(v.x - __half2float(h0));
    __half l1 = __float2half_rn(v.y - __half2float(h1));
    __half l2 = __float2half_rn(v.z - __half2float(h2));
    __half l3 = __float2half_rn(v.w - __half2float(h3));
    __half* base = g_B + (size_t)r * KP;
    *(__half2*)(base + d)            = __halves2half2(h0, h1);
    *(__half2*)(base + d + 2)        = __halves2half2(h2, h3);
    *(__half2*)(base + 512 + d)      = __halves2half2(h0, h1);
    *(__half2*)(base + 512 + d + 2)  = __halves2half2(h2, h3);
    *(__half2*)(base + 1024 + d)     = __halves2half2(l0, l1);
    *(__half2*)(base + 1024 + d + 2) = __halves2half2(l2, l3);
}

__global__ void ehalf_kernel(const float* __restrict__ embed) {
    int w = threadIdx.x >> 5, lane = threadIdx.x & 31;
    int r = blockIdx.x * 8 + w;
    const float* p = embed + (size_t)r * DIM;
    float s = 0.f;
#pragma unroll
    for (int i = 0; i < DIM / 32; i++) { float v = p[lane + i * 32]; s += v * v; }
#pragma unroll
    for (int o = 16; o; o >>= 1) s += __shfl_xor_sync(0xffffffffu, s, o);
    if (lane == 0) g_ehalf[r] = 0.5f * s;
}

// --------------------------------------------------------------- GEMM + top2
__device__ __forceinline__ void stage_chunk(uint32_t sa, int m0, int n0, int c, int tid) {
    const char* abase = (const char*)g_A + ((size_t)m0 * KP + (size_t)c * CH) * 2;
    const char* bbase = (const char*)g_B + ((size_t)n0 * KP + (size_t)c * CH) * 2;
#pragma unroll
    for (int i = 0; i < 4; i++) {
        int idx = tid + i * 256;
        int row = idx >> 3;
        uint32_t off = (uint32_t)idx << 4;
        uint32_t sw = off ^ ((off >> 3) & 0x70);
        CP16(sa + sw, abase + (size_t)row * (KP * 2) + ((idx & 7) << 4));
    }
#pragma unroll
    for (int i = 0; i < 4; i++) {
        int idx = tid + i * 256;
        int row = idx >> 3;
        uint32_t off = (uint32_t)idx << 4;
        uint32_t sw = off ^ ((off >> 3) & 0x70);
        CP16(sa + 16384u + sw, bbase + (size_t)row * (KP * 2) + ((idx & 7) << 4));
    }
}

__global__ __launch_bounds__(256, 1) void gemm_kernel() {
    extern __shared__ char dyn[];
    __shared__ float s_eh[NT];

    const int tid = threadIdx.x;
    const int wid = tid >> 5, lane = tid & 31;
    const int warp_m = wid & 1;          // 0..1 -> 64-row half
    const int warp_n = wid >> 1;         // 0..3 -> 32-col quarter
    const int m0 = blockIdx.x * MT;
    const int n0 = blockIdx.y * NT;
    const int grp = lane >> 2, tg = lane & 3;
    const int lrow = lane & 15;
    const int lcol = (lane >> 4) << 4;   // 0 or 16 bytes

    const uint32_t base = (smem_u32(dyn) + 1023u) & ~1023u;

    float acc[4][4][4];
#pragma unroll
    for (int mi = 0; mi < 4; mi++)
#pragma unroll
        for (int ni = 0; ni < 4; ni++)
#pragma unroll
            for (int j = 0; j < 4; j++) acc[mi][ni][j] = 0.f;

#pragma unroll
    for (int s = 0; s < NSTG; s++) {
        stage_chunk(base + s * STAGE_BYTES, m0, n0, s, tid);
        CP_COMMIT();
    }

#pragma unroll 1
    for (int c = 0; c < NCH; c++) {
        CP_WAITG(NSTG - 1);
        __syncthreads();
        const uint32_t sa = base + (c % NSTG) * STAGE_BYTES;
        const uint32_t sb = sa + 16384u;
#pragma unroll
        for (int ks = 0; ks < 4; ks++) {
            uint32_t a[4][4], bq[2][4];
#pragma unroll
            for (int mi = 0; mi < 4; mi++) {
                uint32_t off = (uint32_t)((warp_m * 64 + mi * 16 + lrow) * 128
                                          + ks * 32 + lcol);
                uint32_t sw = off ^ ((off >> 3) & 0x70);
                LDSM4(a[mi][0], a[mi][1], a[mi][2], a[mi][3], sa + sw);
            }
#pragma unroll
            for (int bi = 0; bi < 2; bi++) {
                uint32_t off = (uint32_t)((warp_n * 32 + bi * 16 + lrow) * 128
                                          + ks * 32 + lcol);
                uint32_t sw = off ^ ((off >> 3) & 0x70);
                LDSM4(bq[bi][0], bq[bi][1], bq[bi][2], bq[bi][3], sb + sw);
            }
#pragma unroll
            for (int mi = 0; mi < 4; mi++)
#pragma unroll
                for (int ni = 0; ni < 4; ni++) {
                    uint32_t b0 = bq[ni >> 1][(ni & 1)];       // k 0..7
                    uint32_t b1 = bq[ni >> 1][(ni & 1) + 2];   // k 8..15
                    MMA16816(acc[mi][ni], a[mi][0], a[mi][1], a[mi][2], a[mi][3],
                             b0, b1);
                }
        }
        __syncthreads();
        if (c + NSTG < NCH)
            stage_chunk(base + (c % NSTG) * STAGE_BYTES, m0, n0, c + NSTG, tid);
        CP_COMMIT();
    }
    CP_WAITG(0);

    if (tid < NT) s_eh[tid] = g_ehalf[n0 + tid];
    __syncthreads();

    // epilogue: per-row top-2 within this warp's 32-column quarter.
    // Each warp owns a distinct partial slot: blockIdx.y*4 + warp_n.
    const int slot = blockIdx.y * 4 + warp_n;
#pragma unroll
    for (int mi = 0; mi < 4; mi++) {
#pragma unroll
        for (int s = 0; s < 2; s++) {
            float v1 = -3.4e38f, v2 = -3.4e38f;
            int i1 = n0;
#pragma unroll
            for (int ni = 0; ni < 4; ni++) {
#pragma unroll
                for (int j = 0; j < 2; j++) {
                    int cl = warp_n * 32 + ni * 8 + tg * 2 + j;
                    float sc = acc[mi][ni][s * 2 + j] - s_eh[cl];
                    if (sc > v1)      { v2 = v1; v1 = sc; i1 = n0 + cl; }
                    else if (sc > v2) { v2 = sc; }
                }
            }
#pragma unroll
            for (int off = 1; off <= 2; off <<= 1) {
                float ov1 = __shfl_xor_sync(0xffffffffu, v1, off);
                float ov2 = __shfl_xor_sync(0xffffffffu, v2, off);
                int   oi  = __shfl_xor_sync(0xffffffffu, i1, off);
                if (ov1 > v1 || (ov1 == v1 && oi < i1)) {
                    v2 = fmaxf(v1, ov2); v1 = ov1; i1 = oi;
                } else {
                    v2 = fmaxf(v2, ov1);
                }
            }
            if (tg == 0) {
                int row = m0 + warp_m * 64 + mi * 16 + s * 8 + grp;
                g_pv1[(size_t)row * NPQ + slot] = v1;
                g_pv2[(size_t)row * NPQ + slot] = v2;
                g_pi1[(size_t)row * NPQ + slot] = i1;
            }
        }
    }
}

// --------------------------------------------------------------- reduce + flag
__global__ void reduce_kernel() {
    int row  = blockIdx.x * 8 + (threadIdx.x >> 5);
    int lane = threadIdx.x & 31;
    size_t b = (size_t)row * NPQ;
    float v1 = -3.4e38f, v2 = -3.4e38f;
    int   i1 = 0x7fffffff;
#pragma unroll
    for (int t = 0; t < NPQ / 32; t++) {
        int s = lane + t * 32;
        float w1 = g_pv1[b + s], w2 = g_pv2[b + s];
        int   j1 = g_pi1[b + s];
        if (w1 > v1 || (w1 == v1 && j1 < i1)) {
            v2 = fmaxf(v1, w2); v1 = w1; i1 = j1;
        } else {
            v2 = fmaxf(v2, w1);
        }
    }
#pragma unroll
    for (int o = 16; o; o >>= 1) {
        float ov1 = __shfl_xor_sync(0xffffffffu, v1, o);
        float ov2 = __shfl_xor_sync(0xffffffffu, v2, o);
        int   oi  = __shfl_xor_sync(0xffffffffu, i1, o);
        if (ov1 > v1 || (ov1 == v1 && oi < i1)) {
            v2 = fmaxf(v1, ov2); v1 = ov1; i1 = oi;
        } else {
            v2 = fmaxf(v2, ov1);
        }
    }
    if (lane == 0) {
        g_ind[row] = i1;
        if (!(v1 - v2 >= EPS_MARGIN)) {
            int p = atomicAdd(&g_flagcnt, 1);
            g_flaglist[p] = row;
        }
    }
}

// --------------------------------------------------------------- fp32 fallback
__global__ __launch_bounds__(256) void fallback_kernel(const float* __restrict__ x,
                                                       const float* __restrict__ embed) {
    __shared__ float xs[DIM];
    __shared__ float wbv[8];
    __shared__ int   wbi[8];
    int tid = threadIdx.x, w = tid >> 5, lane = tid & 31;
    int cnt = g_flagcnt;
    for (int f = blockIdx.x; f < cnt; f += gridDim.x) {
        int row = g_flaglist[f];
        xs[tid]       = x[(size_t)row * DIM + tid];
        xs[tid + 256] = x[(size_t)row * DIM + tid + 256];
        __syncthreads();
        float best = -3.4e38f; int bi = 0;
        for (int code = w * 1024; code < (w + 1) * 1024; code++) {
            const float* e = embed + (size_t)code * DIM;
            float a = 0.f;
#pragma unroll
            for (int i = 0; i < 16; i++) a += xs[lane + 32 * i] * e[lane + 32 * i];
#pragma unroll
            for (int o = 16; o; o >>= 1) a += __shfl_xor_sync(0xffffffffu, a, o);
            float s = a - g_ehalf[code];
            if (s > best) { best = s; bi = code; }
        }
        if (lane == 0) { wbv[w] = best; wbi[w] = bi; }
        __syncthreads();
        if (tid == 0) {
            float bv = wbv[0]; int b = wbi[0];
#pragma unroll
            for (int j = 1; j < 8; j++)
                if (wbv[j] > bv) { bv = wbv[j]; b = wbi[j]; }
            g_ind[row] = b;
        }
        __syncthreads();
    }
}

// --------------------------------------------------------------- gather
__global__ void gather_kernel(const float* __restrict__ embed,
                              float* __restrict__ outq,
                              float* __restrict__ iout) {
    int row = blockIdx.x;
    int idx = g_ind[row];
    if (outq) {
        const float4* src = (const float4*)(embed + (size_t)idx * DIM);
        float4*       dst = (float4*)(outq + (size_t)row * DIM);
        dst[threadIdx.x] = src[threadIdx.x];
    }
    if (iout && threadIdx.x == 0) iout[row] = (float)idx;
}

// ---------------------------------------------------------------------------
extern "C" void kernel_launch(void* const* d_in, const int* in_sizes, int n_in,
                              void* d_out, int out_size) {
    const float* x = nullptr;
    const float* embed = nullptr;
    for (int i = 0; i < n_in; i++) {
        if (in_sizes[i] == NROWS * DIM)    x = (const float*)d_in[i];
        else if (in_sizes[i] == KCB * DIM) embed = (const float*)d_in[i];
    }

    float* out  = (float*)d_out;
    float* qout = nullptr;
    float* iout = nullptr;
    if (out_size >= NROWS * DIM + NROWS) { qout = out; iout = out + (size_t)NROWS * DIM; }
    else if (out_size >= NROWS * DIM)    { qout = out; }
    else                                 { iout = out; }

    cudaFuncSetAttribute(gemm_kernel, cudaFuncAttributeMaxDynamicSharedMemorySize,
                         DYN_SMEM);

    split_x_kernel<<<NROWS / 2, 256>>>(x);
    split_e_kernel<<<KCB / 2, 256>>>(embed);
    ehalf_kernel<<<KCB / 8, 256>>>(embed);
    gemm_kernel<<<dim3(NROWS / MT, KCB / NT), 256, DYN_SMEM>>>();
    reduce_kernel<<<NROWS / 8, 256>>>();
    fallback_kernel<<<128, 256>>>(x, embed);
    gather_kernel<<<NROWS, 128>>>(embed, qout, iout);
}

// round 15
// speedup vs baseline: 4.2268x; 4.1994x over previous
#include <cuda_runtime.h>
#include <cuda_fp16.h>
#include <cstdint>

#define DIM   512
#define NROWS 16384
#define KCB   8192
#define KP    512             // hh-screen only: K' = DIM
#define CH    64              // K elems per chunk (128 bytes fp16)
#define NCH   (KP / CH)       // 8
#define NSTG  3
#define STAGE_BYTES 32768     // A(128x128B)=16K + B(128x128B)=16K
#define DYN_SMEM (NSTG * STAGE_BYTES + 1024)
#define MT    128
#define NT    128
#define NPQ   ((KCB / NT) * 4)   // 256 partials per row
#define EPS_MARGIN 0.12f

__device__ __half g_A[(size_t)NROWS * KP];
__device__ __half g_B[(size_t)KCB * KP];
__device__ float  g_ehalf[KCB];
__device__ float  g_pv1[(size_t)NROWS * NPQ];
__device__ float  g_pv2[(size_t)NROWS * NPQ];
__device__ int    g_pi1[(size_t)NROWS * NPQ];
__device__ int    g_ind[NROWS];
__device__ int    g_flagcnt;
__device__ int    g_flaglist[NROWS];
__device__ unsigned long long g_best[NROWS];

// ---------------------------------------------------------------- PTX helpers
__device__ __forceinline__ uint32_t smem_u32(const void* p) {
    return (uint32_t)__cvta_generic_to_shared(p);
}
#define CP16(dst, src) \
    asm volatile("cp.async.cg.shared.global [%0], [%1], 16;" :: "r"(dst), "l"(src))
#define CP_COMMIT() asm volatile("cp.async.commit_group;" ::: "memory")
#define CP_WAITG(n) asm volatile("cp.async.wait_group %0;" :: "n"(n) : "memory")

#define LDSM4(r0, r1, r2, r3, a)                                              \
    asm volatile("ldmatrix.sync.aligned.m8n8.x4.shared.b16 {%0,%1,%2,%3},[%4];" \
                 : "=r"(r0), "=r"(r1), "=r"(r2), "=r"(r3) : "r"(a))

#define MMA16816(d, a0, a1, a2, a3, b0, b1)                                   \
    asm volatile("mma.sync.aligned.m16n8k16.row.col.f32.f16.f16.f32 "         \
                 "{%0,%1,%2,%3},{%4,%5,%6,%7},{%8,%9},{%0,%1,%2,%3};"         \
                 : "+f"((d)[0]), "+f"((d)[1]), "+f"((d)[2]), "+f"((d)[3])     \
                 : "r"(a0), "r"(a1), "r"(a2), "r"(a3), "r"(b0), "r"(b1))

#define FMA2(acc, a, b) \
    asm volatile("fma.rn.f32x2 %0, %1, %2, %0;" : "+l"(acc) : "l"(a), "l"(b))
#define PACK2(d, lo, hi) \
    asm volatile("mov.b64 %0, {%1, %2};" : "=l"(d) : "f"(lo), "f"(hi))
#define UNPK2(lo, hi, s) \
    asm volatile("mov.b64 {%0, %1}, %2;" : "=f"(lo), "=f"(hi) : "l"(s))

// ----------------------------------------------------- convert (device globals)
__global__ void cvt_x_kernel(const float* __restrict__ src) {
    int idx = blockIdx.x * 256 + threadIdx.x;
    float4 v = ((const float4*)src)[idx];
    ((__half2*)g_A)[idx * 2]     = __floats2half2_rn(v.x, v.y);
    ((__half2*)g_A)[idx * 2 + 1] = __floats2half2_rn(v.z, v.w);
}

__global__ void cvt_e_kernel(const float* __restrict__ src) {
    int idx = blockIdx.x * 256 + threadIdx.x;
    float4 v = ((const float4*)src)[idx];
    ((__half2*)g_B)[idx * 2]     = __floats2half2_rn(v.x, v.y);
    ((__half2*)g_B)[idx * 2 + 1] = __floats2half2_rn(v.z, v.w);
}

__global__ void ehalf_kernel(const float* __restrict__ embed) {
    if (blockIdx.x == 0 && threadIdx.x == 0) g_flagcnt = 0;
    int w = threadIdx.x >> 5, lane = threadIdx.x & 31;
    int r = blockIdx.x * 8 + w;
    const float* p = embed + (size_t)r * DIM;
    float s = 0.f;
#pragma unroll
    for (int i = 0; i < DIM / 32; i++) { float v = p[lane + i * 32]; s += v * v; }
#pragma unroll
    for (int o = 16; o; o >>= 1) s += __shfl_xor_sync(0xffffffffu, s, o);
    if (lane == 0) g_ehalf[r] = 0.5f * s;
}

// --------------------------------------------------------------- GEMM + top2
__device__ __forceinline__ void stage_chunk(uint32_t sa, int m0, int n0, int c, int tid) {
    const char* abase = (const char*)g_A + ((size_t)m0 * KP + (size_t)c * CH) * 2;
    const char* bbase = (const char*)g_B + ((size_t)n0 * KP + (size_t)c * CH) * 2;
#pragma unroll
    for (int i = 0; i < 4; i++) {
        int idx = tid + i * 256;
        int row = idx >> 3;
        uint32_t off = (uint32_t)idx << 4;
        uint32_t sw = off ^ ((off >> 3) & 0x70);
        CP16(sa + sw, abase + (size_t)row * (KP * 2) + ((idx & 7) << 4));
    }
#pragma unroll
    for (int i = 0; i < 4; i++) {
        int idx = tid + i * 256;
        int row = idx >> 3;
        uint32_t off = (uint32_t)idx << 4;
        uint32_t sw = off ^ ((off >> 3) & 0x70);
        CP16(sa + 16384u + sw, bbase + (size_t)row * (KP * 2) + ((idx & 7) << 4));
    }
}

__global__ __launch_bounds__(256, 2) void gemm_kernel() {
    extern __shared__ char dyn[];
    __shared__ float s_eh[NT];

    const int tid = threadIdx.x;
    const int wid = tid >> 5, lane = tid & 31;
    const int warp_m = wid & 1;
    const int warp_n = wid >> 1;
    const int m0 = blockIdx.x * MT;
    const int n0 = blockIdx.y * NT;
    const int grp = lane >> 2, tg = lane & 3;
    const int lrow = lane & 15;
    const int lcol = (lane >> 4) << 4;

    const uint32_t base = (smem_u32(dyn) + 1023u) & ~1023u;

    float acc[4][4][4];
#pragma unroll
    for (int mi = 0; mi < 4; mi++)
#pragma unroll
        for (int ni = 0; ni < 4; ni++)
#pragma unroll
            for (int j = 0; j < 4; j++) acc[mi][ni][j] = 0.f;

#pragma unroll
    for (int s = 0; s < NSTG; s++) {
        stage_chunk(base + s * STAGE_BYTES, m0, n0, s, tid);
        CP_COMMIT();
    }

#pragma unroll 1
    for (int c = 0; c < NCH; c++) {
        CP_WAITG(NSTG - 1);
        __syncthreads();
        const uint32_t sa = base + (c % NSTG) * STAGE_BYTES;
        const uint32_t sb = sa + 16384u;
#pragma unroll
        for (int ks = 0; ks < 4; ks++) {
            uint32_t a[4][4], bq[2][4];
#pragma unroll
            for (int mi = 0; mi < 4; mi++) {
                uint32_t off = (uint32_t)((warp_m * 64 + mi * 16 + lrow) * 128
                                          + ks * 32 + lcol);
                uint32_t sw = off ^ ((off >> 3) & 0x70);
                LDSM4(a[mi][0], a[mi][1], a[mi][2], a[mi][3], sa + sw);
            }
#pragma unroll
            for (int bi = 0; bi < 2; bi++) {
                uint32_t off = (uint32_t)((warp_n * 32 + bi * 16 + lrow) * 128
                                          + ks * 32 + lcol);
                uint32_t sw = off ^ ((off >> 3) & 0x70);
                LDSM4(bq[bi][0], bq[bi][1], bq[bi][2], bq[bi][3], sb + sw);
            }
#pragma unroll
            for (int mi = 0; mi < 4; mi++)
#pragma unroll
                for (int ni = 0; ni < 4; ni++) {
                    uint32_t b0 = bq[ni >> 1][(ni & 1)];
                    uint32_t b1 = bq[ni >> 1][(ni & 1) + 2];
                    MMA16816(acc[mi][ni], a[mi][0], a[mi][1], a[mi][2], a[mi][3],
                             b0, b1);
                }
        }
        __syncthreads();
        if (c + NSTG < NCH)
            stage_chunk(base + (c % NSTG) * STAGE_BYTES, m0, n0, c + NSTG, tid);
        CP_COMMIT();
    }
    CP_WAITG(0);

    if (tid < NT) s_eh[tid] = g_ehalf[n0 + tid];
    __syncthreads();

    const int slot = blockIdx.y * 4 + warp_n;
#pragma unroll
    for (int mi = 0; mi < 4; mi++) {
#pragma unroll
        for (int s = 0; s < 2; s++) {
            float v1 = -3.4e38f, v2 = -3.4e38f;
            int i1 = n0;
#pragma unroll
            for (int ni = 0; ni < 4; ni++) {
#pragma unroll
                for (int j = 0; j < 2; j++) {
                    int cl = warp_n * 32 + ni * 8 + tg * 2 + j;
                    float sc = acc[mi][ni][s * 2 + j] - s_eh[cl];
                    if (sc > v1)      { v2 = v1; v1 = sc; i1 = n0 + cl; }
                    else if (sc > v2) { v2 = sc; }
                }
            }
#pragma unroll
            for (int off = 1; off <= 2; off <<= 1) {
                float ov1 = __shfl_xor_sync(0xffffffffu, v1, off);
                float ov2 = __shfl_xor_sync(0xffffffffu, v2, off);
                int   oi  = __shfl_xor_sync(0xffffffffu, i1, off);
                if (ov1 > v1 || (ov1 == v1 && oi < i1)) {
                    v2 = fmaxf(v1, ov2); v1 = ov1; i1 = oi;
                } else {
                    v2 = fmaxf(v2, ov1);
                }
            }
            if (tg == 0) {
                int row = m0 + warp_m * 64 + mi * 16 + s * 8 + grp;
                g_pv1[(size_t)row * NPQ + slot] = v1;
                g_pv2[(size_t)row * NPQ + slot] = v2;
                g_pi1[(size_t)row * NPQ + slot] = i1;
            }
        }
    }
}

// --------------------------------------------------------------- reduce + flag
__global__ void reduce_kernel() {
    int row  = blockIdx.x * 8 + (threadIdx.x >> 5);
    int lane = threadIdx.x & 31;
    size_t b = (size_t)row * NPQ;
    float v1 = -3.4e38f, v2 = -3.4e38f;
    int   i1 = 0x7fffffff;
#pragma unroll
    for (int t = 0; t < NPQ / 32; t++) {
        int s = lane + t * 32;
        float w1 = g_pv1[b + s], w2 = g_pv2[b + s];
        int   j1 = g_pi1[b + s];
        if (w1 > v1 || (w1 == v1 && j1 < i1)) {
            v2 = fmaxf(v1, w2); v1 = w1; i1 = j1;
        } else {
            v2 = fmaxf(v2, w1);
        }
    }
#pragma unroll
    for (int o = 16; o; o >>= 1) {
        float ov1 = __shfl_xor_sync(0xffffffffu, v1, o);
        float ov2 = __shfl_xor_sync(0xffffffffu, v2, o);
        int   oi  = __shfl_xor_sync(0xffffffffu, i1, o);
        if (ov1 > v1 || (ov1 == v1 && oi < i1)) {
            v2 = fmaxf(v1, ov2); v1 = ov1; i1 = oi;
        } else {
            v2 = fmaxf(v2, ov1);
        }
    }
    if (lane == 0) {
        g_ind[row] = i1;
        if (!(v1 - v2 >= EPS_MARGIN)) {
            int p = atomicAdd(&g_flagcnt, 1);
            g_flaglist[p] = row;
            g_best[row] = 0ull;
        }
    }
}

// -------------------------------------------------- exact fp32 fallback (4-row)
__global__ __launch_bounds__(256) void fallback_kernel(const float* __restrict__ x,
                                                       const float* __restrict__ embed) {
    int cnt = g_flagcnt;
    int lane = threadIdx.x & 31, wid = threadIdx.x >> 5;
    for (int g = blockIdx.x; g * 4 < cnt; g += gridDim.x) {
        int rows[4];
#pragma unroll
        for (int j = 0; j < 4; j++) {
            int f = g * 4 + j;
            rows[j] = g_flaglist[f < cnt ? f : cnt - 1];
        }
        unsigned long long xp01[16], xp23[16];
#pragma unroll
        for (int i = 0; i < 16; i++) {
            float a0 = x[(size_t)rows[0] * DIM + lane + 32 * i];
            float a1 = x[(size_t)rows[1] * DIM + lane + 32 * i];
            float a2 = x[(size_t)rows[2] * DIM + lane + 32 * i];
            float a3 = x[(size_t)rows[3] * DIM + lane + 32 * i];
            PACK2(xp01[i], a0, a1);
            PACK2(xp23[i], a2, a3);
        }
        unsigned long long bp[4] = {0ull, 0ull, 0ull, 0ull};
        int c0 = blockIdx.y * 2048 + wid * 256;
        for (int c = c0; c < c0 + 256; c++) {
            const float* e = embed + (size_t)c * DIM;
            unsigned long long a01 = 0ull, a23 = 0ull;
#pragma unroll
            for (int i = 0; i < 16; i++) {
                float ev = e[lane + 32 * i];
                unsigned long long ed;
                PACK2(ed, ev, ev);
                FMA2(a01, xp01[i], ed);
                FMA2(a23, xp23[i], ed);
            }
            float d0, d1, d2, d3;
            UNPK2(d0, d1, a01);
            UNPK2(d2, d3, a23);
#pragma unroll
            for (int o = 16; o; o >>= 1) {
                d0 += __shfl_xor_sync(0xffffffffu, d0, o);
                d1 += __shfl_xor_sync(0xffffffffu, d1, o);
                d2 += __shfl_xor_sync(0xffffffffu, d2, o);
                d3 += __shfl_xor_sync(0xffffffffu, d3, o);
            }
            float eh = g_ehalf[c];
            float s[4] = {d0 - eh, d1 - eh, d2 - eh, d3 - eh};
#pragma unroll
            for (int j = 0; j < 4; j++) {
                unsigned int u = __float_as_uint(s[j]);
                u = (u & 0x80000000u) ? ~u : (u | 0x80000000u);
                unsigned long long pk =
                    ((unsigned long long)u << 32) | (unsigned)(8191 - c);
                if (pk > bp[j]) bp[j] = pk;
            }
        }
        if (lane == 0) {
#pragma unroll
            for (int j = 0; j < 4; j++) atomicMax(&g_best[rows[j]], bp[j]);
        }
    }
}

__global__ void commit_kernel() {
    int f = blockIdx.x * 256 + threadIdx.x;
    if (f < g_flagcnt) {
        int row = g_flaglist[f];
        g_ind[row] = 8191 - (int)(g_best[row] & 0x3FFFull);
    }
}

// --------------------------------------------------------------- gather
__global__ void gather_kernel(const float* __restrict__ embed,
                              float* __restrict__ outq,
                              float* __restrict__ iout) {
    int row = blockIdx.x;
    int idx = g_ind[row];
    if (outq) {
        const float4* src = (const float4*)(embed + (size_t)idx * DIM);
        float4*       dst = (float4*)(outq + (size_t)row * DIM);
        dst[threadIdx.x] = src[threadIdx.x];
    }
    if (iout && threadIdx.x == 0) iout[row] = (float)idx;
}

// ---------------------------------------------------------------------------
extern "C" void kernel_launch(void* const* d_in, const int* in_sizes, int n_in,
                              void* d_out, int out_size) {
    const float* x = nullptr;
    const float* embed = nullptr;
    for (int i = 0; i < n_in; i++) {
        if (in_sizes[i] == NROWS * DIM)    x = (const float*)d_in[i];
        else if (in_sizes[i] == KCB * DIM) embed = (const float*)d_in[i];
    }

    float* out  = (float*)d_out;
    float* qout = nullptr;
    float* iout = nullptr;
    if (out_size >= NROWS * DIM + NROWS) { qout = out; iout = out + (size_t)NROWS * DIM; }
    else if (out_size >= NROWS * DIM)    { qout = out; }
    else                                 { iout = out; }

    cudaFuncSetAttribute(gemm_kernel, cudaFuncAttributeMaxDynamicSharedMemorySize,
                         DYN_SMEM);

    cvt_x_kernel<<<NROWS * DIM / 4 / 256, 256>>>(x);
    cvt_e_kernel<<<KCB * DIM / 4 / 256, 256>>>(embed);
    ehalf_kernel<<<KCB / 8, 256>>>(embed);
    gemm_kernel<<<dim3(NROWS / MT, KCB / NT), 256, DYN_SMEM>>>();
    reduce_kernel<<<NROWS / 8, 256>>>();
    fallback_kernel<<<dim3(128, 4), 256>>>(x, embed);
    commit_kernel<<<NROWS / 256, 256>>>();
    gather_kernel<<<NROWS, 128>>>(embed, qout, iout);
}